// round 14
// baseline (speedup 1.0000x reference)
#include <cuda_runtime.h>
#include <cuda_bf16.h>
#include <cstdint>
#include <cstddef>

#define HID   1024
#define BATCH 256
#define SEQ   512
#define VOCAB 32000
#define G3    3072   // 3*HID

// persistent-scan geometry
#define NCTA  128
#define GRPCTA 64         // CTAs per independent barrier group (one per batch half)
#define UNITS 16          // hidden units per CTA
#define NROWS 48          // 3 gates * UNITS
#define MCTA  128         // batch rows per CTA
#define KT    64          // K iterations of 16

// dynamic smem layout (bytes): W fragment-major hi/lo + Hg staging
#define OFF_WFH 0
#define WF_WORDS (6 * 64 * 32 * 2)            // 24576 uint32 per plane
#define OFF_WFL (WF_WORDS * 4)                // 98304
#define OFF_HG  (2 * WF_WORDS * 4)            // 196608
#define HG_STRIDE 51
#define SMEM_TOTAL (OFF_HG + MCTA * HG_STRIDE * 4)   // 222720

// ---------------- persistent scratch ----------------
__device__ __nv_bfloat16 g_Wih_hi[G3 * HID];
__device__ __nv_bfloat16 g_Wih_lo[G3 * HID];
__device__ __nv_bfloat16 g_Whh_hi[G3 * HID];
__device__ __nv_bfloat16 g_Whh_lo[G3 * HID];
__device__ float         g_E[(size_t)VOCAB * G3];   // emb @ W_ih^T
// h state, double-buffered, FRAGMENT-MAJOR bf16 planes:
// index ((m*64 + kt)*32 + lane)*4 + word, word order = {(g,c2),(g+8,c2),(g,c2+8),(g+8,c2+8)}
__device__ unsigned g_hfh[2][16 * 64 * 32 * 4];
__device__ unsigned g_hfl[2][16 * 64 * 32 * 4];
// h state, double-buffered linear fp32 (epilogue h_prev read + dense head)
__device__ float    g_hlin[2][BATCH * HID];
__device__ unsigned g_count2[2] = {0, 0};
__device__ unsigned g_phase2[2] = {0, 0};

// ---------------- helpers ----------------
__device__ __forceinline__ void split2(float x, __nv_bfloat16 &hi, __nv_bfloat16 &lo) {
    hi = __float2bfloat16_rn(x);
    lo = __float2bfloat16_rn(x - __bfloat162float(hi));
}
__device__ __forceinline__ unsigned pk(__nv_bfloat16 a, __nv_bfloat16 b) {
    return (unsigned)__bfloat16_as_ushort(a) | ((unsigned)__bfloat16_as_ushort(b) << 16);
}
__device__ __forceinline__ void mma16816(float *d, const unsigned *a, const unsigned *b) {
    asm volatile(
        "mma.sync.aligned.m16n8k16.row.col.f32.bf16.bf16.f32 "
        "{%0,%1,%2,%3},{%4,%5,%6,%7},{%8,%9},{%0,%1,%2,%3};\n"
        : "+f"(d[0]), "+f"(d[1]), "+f"(d[2]), "+f"(d[3])
        : "r"(a[0]), "r"(a[1]), "r"(a[2]), "r"(a[3]), "r"(b[0]), "r"(b[1]));
}
__device__ __forceinline__ float sigf(float x) { return 1.0f / (1.0f + __expf(-x)); }

// Grid barrier over one 64-CTA group (batch half), hang-proofed bounded spin.
__device__ __forceinline__ void grid_bar(int grp, unsigned target) {
    __threadfence();
    __syncthreads();
    if (threadIdx.x == 0) {
        unsigned a = atomicAdd(&g_count2[grp], 1u);
        if (a == GRPCTA - 1) {
            g_count2[grp] = 0;
            __threadfence();
            atomicExch(&g_phase2[grp], target);
        } else {
            for (int spin = 0; spin < 200000; ++spin) {
                if (atomicAdd(&g_phase2[grp], 0u) == target) break;
                __nanosleep(64);
            }
        }
        __threadfence();
    }
    __syncthreads();
}

// ---------------- kernel: split weights into bf16 hi/lo ----------------
__global__ void k_split(const float *__restrict__ Wih, const float *__restrict__ Whh) {
    int i = blockIdx.x * blockDim.x + threadIdx.x;
    const int N = G3 * HID;
    if (i < N) {
        split2(Wih[i], g_Wih_hi[i], g_Wih_lo[i]);
    } else {
        int j = i - N;
        split2(Whh[j], g_Whh_hi[j], g_Whh_lo[j]);
    }
}

// ---------------- kernel: E = emb @ W_ih^T  (M=32000, N=3072, K=1024) ----------------
__global__ __launch_bounds__(256) void k_vocab(const float *__restrict__ emb) {
    __shared__ __nv_bfloat16 sA_hi[128 * 40];
    __shared__ __nv_bfloat16 sA_lo[128 * 40];
    __shared__ __nv_bfloat16 sB_hi[128 * 40];
    __shared__ __nv_bfloat16 sB_lo[128 * 40];

    const int tid = threadIdx.x;
    const int lane = tid & 31, warp = tid >> 5;
    const int wm = warp & 1, wn = warp >> 1;
    const int m0 = blockIdx.y * 128, n0 = blockIdx.x * 128;

    float acc[4][4][4] = {};
    const int g  = lane >> 2;
    const int c2 = (lane & 3) * 2;

    for (int kt = 0; kt < 32; ++kt) {
        const int k0 = kt * 32;
        __syncthreads();
        {
            const int r_ = tid >> 3, c4 = (tid & 7) * 4;
#pragma unroll
            for (int i = 0; i < 4; i++) {
                const int row = r_ + i * 32;
                float4 v = *reinterpret_cast<const float4 *>(
                    &emb[(size_t)(m0 + row) * HID + k0 + c4]);
                __nv_bfloat16 h0, h1, h2, h3, l0, l1, l2, l3;
                split2(v.x, h0, l0); split2(v.y, h1, l1);
                split2(v.z, h2, l2); split2(v.w, h3, l3);
                unsigned *ph = reinterpret_cast<unsigned *>(&sA_hi[row * 40 + c4]);
                ph[0] = pk(h0, h1); ph[1] = pk(h2, h3);
                unsigned *pl = reinterpret_cast<unsigned *>(&sA_lo[row * 40 + c4]);
                pl[0] = pk(l0, l1); pl[1] = pk(l2, l3);
            }
        }
        {
            const int rb = tid >> 2, q = tid & 3;
#pragma unroll
            for (int i = 0; i < 2; i++) {
                const int row = rb + i * 64;
                *reinterpret_cast<uint4 *>(&sB_hi[row * 40 + q * 8]) =
                    *reinterpret_cast<const uint4 *>(&g_Wih_hi[(size_t)(n0 + row) * HID + k0 + q * 8]);
                *reinterpret_cast<uint4 *>(&sB_lo[row * 40 + q * 8]) =
                    *reinterpret_cast<const uint4 *>(&g_Wih_lo[(size_t)(n0 + row) * HID + k0 + q * 8]);
            }
        }
        __syncthreads();

#pragma unroll
        for (int kk = 0; kk < 32; kk += 16) {
            unsigned ah[4][4], al[4][4];
#pragma unroll
            for (int mf = 0; mf < 4; mf++) {
                const int ra = wm * 64 + mf * 16 + g;
                ah[mf][0] = *reinterpret_cast<unsigned *>(&sA_hi[ra * 40 + kk + c2]);
                ah[mf][1] = *reinterpret_cast<unsigned *>(&sA_hi[(ra + 8) * 40 + kk + c2]);
                ah[mf][2] = *reinterpret_cast<unsigned *>(&sA_hi[ra * 40 + kk + c2 + 8]);
                ah[mf][3] = *reinterpret_cast<unsigned *>(&sA_hi[(ra + 8) * 40 + kk + c2 + 8]);
                al[mf][0] = *reinterpret_cast<unsigned *>(&sA_lo[ra * 40 + kk + c2]);
                al[mf][1] = *reinterpret_cast<unsigned *>(&sA_lo[(ra + 8) * 40 + kk + c2]);
                al[mf][2] = *reinterpret_cast<unsigned *>(&sA_lo[ra * 40 + kk + c2 + 8]);
                al[mf][3] = *reinterpret_cast<unsigned *>(&sA_lo[(ra + 8) * 40 + kk + c2 + 8]);
            }
#pragma unroll
            for (int nf = 0; nf < 4; nf++) {
                const int rb_ = wn * 32 + nf * 8 + g;
                unsigned bh[2], bl[2];
                bh[0] = *reinterpret_cast<unsigned *>(&sB_hi[rb_ * 40 + kk + c2]);
                bh[1] = *reinterpret_cast<unsigned *>(&sB_hi[rb_ * 40 + kk + c2 + 8]);
                bl[0] = *reinterpret_cast<unsigned *>(&sB_lo[rb_ * 40 + kk + c2]);
                bl[1] = *reinterpret_cast<unsigned *>(&sB_lo[rb_ * 40 + kk + c2 + 8]);
#pragma unroll
                for (int mf = 0; mf < 4; mf++) {
                    mma16816(acc[mf][nf], ah[mf], bh);
                    mma16816(acc[mf][nf], ah[mf], bl);
                    mma16816(acc[mf][nf], al[mf], bh);
                }
            }
        }
    }

#pragma unroll
    for (int mf = 0; mf < 4; mf++) {
#pragma unroll
        for (int nf = 0; nf < 4; nf++) {
            const int row = m0 + wm * 64 + mf * 16 + g;
            const int col = n0 + wn * 32 + nf * 8 + c2;
            *reinterpret_cast<float2 *>(&g_E[(size_t)row * G3 + col]) =
                make_float2(acc[mf][nf][0], acc[mf][nf][1]);
            *reinterpret_cast<float2 *>(&g_E[(size_t)(row + 8) * G3 + col]) =
                make_float2(acc[mf][nf][2], acc[mf][nf][3]);
        }
    }
}

// ---------------- persistent scan: 512 threads, 4 K-quarters x 4 M-quarters ----------------
__global__ __launch_bounds__(512, 1) void k_scan(const int *__restrict__ inputs,
                                                 const float *__restrict__ b_ih,
                                                 const float *__restrict__ b_hh) {
    extern __shared__ char smem[];
    unsigned *sWfH = reinterpret_cast<unsigned *>(smem + OFF_WFH);
    unsigned *sWfL = reinterpret_cast<unsigned *>(smem + OFF_WFL);
    float *sHg = reinterpret_cast<float *>(smem + OFF_HG);

    const int tid  = threadIdx.x;
    const int lane = tid & 31, warp = tid >> 5;   // 16 warps
    const int kh = warp >> 2;                     // K quarter (0..3)
    const int mq = warp & 3;                      // M quarter
    const int bt = blockIdx.x >> 6, ut = blockIdx.x & 63;
    const int b0 = bt * MCTA, j0 = ut * UNITS;
    const int g  = lane >> 2;
    const int c2 = (lane & 3) * 2;

    // ---- build fragment-major W_hh slab in smem (once) ----
    for (int i = tid; i < 6 * 64 * 32; i += 512) {
        const int nf = i >> 11, kt = (i >> 5) & 63, l = i & 31;
        const int g_ = l >> 2, cc = (l & 3) * 2;
        const int sr = nf * 8 + g_;
        const int wrow = (sr >> 4) * HID + j0 + (sr & 15);
        const size_t base = (size_t)wrow * HID + kt * 16 + cc;
        sWfH[(size_t)i * 2 + 0] = *reinterpret_cast<const unsigned *>(&g_Whh_hi[base]);
        sWfH[(size_t)i * 2 + 1] = *reinterpret_cast<const unsigned *>(&g_Whh_hi[base + 8]);
        sWfL[(size_t)i * 2 + 0] = *reinterpret_cast<const unsigned *>(&g_Whh_lo[base]);
        sWfL[(size_t)i * 2 + 1] = *reinterpret_cast<const unsigned *>(&g_Whh_lo[base + 8]);
    }

    // ---- epilogue mapping: thread -> (batch row, 4 units) ----
    const int er = tid >> 2;            // batch row 0..127
    const int u0 = (tid & 3) * 4;       // unit quarter
    const size_t hoff = (size_t)(b0 + er) * HID + j0 + u0;   // linear fp32 h offset
    // fragment-store mapping: this thread's 4 units = 2 (lane, word) pairs
    const int m_w  = bt * 8 + (er >> 4);
    const int rr   = er & 15;
    const int wIdx = ((rr >= 8) ? 1 : 0) + ((u0 >= 8) ? 2 : 0);
    const int l0   = (rr & 7) * 4 + ((u0 & 7) >> 1);
    const size_t fragW = ((size_t)(m_w * 64 + ut) * 32 + l0) * 4 + wIdx;
    __syncthreads();

    // this warp's two M-fragments and K-quarter
    const int m0f = bt * 8 + mq * 2;
    const int kt0 = kh * 16;
    const size_t aidx0 = ((size_t)(m0f + 0) * 64 + kt0) * 32 + lane;
    const size_t aidx1 = ((size_t)(m0f + 1) * 64 + kt0) * 32 + lane;

    for (int t = 0; t < SEQ; t++) {
        const int rp = t & 1, wp = rp ^ 1;
        const uint4 *AH = reinterpret_cast<const uint4 *>(g_hfh[rp]);
        const uint4 *AL = reinterpret_cast<const uint4 *>(g_hfl[rp]);

        // ---- prefetch E-gather rows + h_prev for epilogue ----
        const int v = inputs[(b0 + er) * SEQ + t];
        const float *Er = &g_E[(size_t)v * G3 + j0 + u0];
        float4 exr = *reinterpret_cast<const float4 *>(Er);
        float4 exz = *reinterpret_cast<const float4 *>(Er + HID);
        float4 exn = *reinterpret_cast<const float4 *>(Er + 2 * HID);
        float4 hpv = __ldcg(reinterpret_cast<const float4 *>(&g_hlin[rp][hoff]));

        float acc[2][6][4] = {};

        // ---- ring-3, distance-2 pipelined K-loop over this warp's 16 kt ----
        uint4 pAh[3][2], pAl[3][2];
#pragma unroll
        for (int s = 0; s < 2; s++) {
            pAh[s][0] = __ldcg(AH + aidx0 + (size_t)s * 32);
            pAh[s][1] = __ldcg(AH + aidx1 + (size_t)s * 32);
            pAl[s][0] = __ldcg(AL + aidx0 + (size_t)s * 32);
            pAl[s][1] = __ldcg(AL + aidx1 + (size_t)s * 32);
        }

#pragma unroll
        for (int k = 0; k < 16; k++) {
            const int slot = k % 3;
            if (k + 2 < 16) {
                const int ns = (k + 2) % 3;
                pAh[ns][0] = __ldcg(AH + aidx0 + (size_t)(k + 2) * 32);
                pAh[ns][1] = __ldcg(AH + aidx1 + (size_t)(k + 2) * 32);
                pAl[ns][0] = __ldcg(AL + aidx0 + (size_t)(k + 2) * 32);
                pAl[ns][1] = __ldcg(AL + aidx1 + (size_t)(k + 2) * 32);
            }
            const int ktg = kt0 + k;
            uint2 bhv[6], blv[6];
            {
                const uint2 *Bh = reinterpret_cast<const uint2 *>(sWfH) + (size_t)ktg * 32 + lane;
                const uint2 *Bl = reinterpret_cast<const uint2 *>(sWfL) + (size_t)ktg * 32 + lane;
#pragma unroll
                for (int nf = 0; nf < 6; nf++) {
                    bhv[nf] = Bh[(size_t)nf * 2048];
                    blv[nf] = Bl[(size_t)nf * 2048];
                }
            }
            unsigned ah0[4] = {pAh[slot][0].x, pAh[slot][0].y, pAh[slot][0].z, pAh[slot][0].w};
            unsigned ah1[4] = {pAh[slot][1].x, pAh[slot][1].y, pAh[slot][1].z, pAh[slot][1].w};
            unsigned al0[4] = {pAl[slot][0].x, pAl[slot][0].y, pAl[slot][0].z, pAl[slot][0].w};
            unsigned al1[4] = {pAl[slot][1].x, pAl[slot][1].y, pAl[slot][1].z, pAl[slot][1].w};
#pragma unroll
            for (int nf = 0; nf < 6; nf++) {
                unsigned *bh = reinterpret_cast<unsigned *>(&bhv[nf]);
                mma16816(acc[0][nf], ah0, bh);
                mma16816(acc[1][nf], ah1, bh);
            }
#pragma unroll
            for (int nf = 0; nf < 6; nf++) {
                unsigned *bl = reinterpret_cast<unsigned *>(&blv[nf]);
                mma16816(acc[0][nf], ah0, bl);
                mma16816(acc[1][nf], ah1, bl);
            }
#pragma unroll
            for (int nf = 0; nf < 6; nf++) {
                unsigned *bh = reinterpret_cast<unsigned *>(&bhv[nf]);
                mma16816(acc[0][nf], al0, bh);
                mma16816(acc[1][nf], al1, bh);
            }
        }

        // ---- K-reduction directly into Hg staging: kh=0 stores, kh>0 atomicAdd ----
        if (kh == 0) {
#pragma unroll
            for (int i = 0; i < 2; i++)
#pragma unroll
                for (int nf = 0; nf < 6; nf++) {
                    const int r0  = (mq * 2 + i) * 16 + g;
                    const int col = nf * 8 + c2;
                    sHg[r0 * HG_STRIDE + col]           = acc[i][nf][0];
                    sHg[r0 * HG_STRIDE + col + 1]       = acc[i][nf][1];
                    sHg[(r0 + 8) * HG_STRIDE + col]     = acc[i][nf][2];
                    sHg[(r0 + 8) * HG_STRIDE + col + 1] = acc[i][nf][3];
                }
        }
        __syncthreads();
        if (kh != 0) {
#pragma unroll
            for (int i = 0; i < 2; i++)
#pragma unroll
                for (int nf = 0; nf < 6; nf++) {
                    const int r0  = (mq * 2 + i) * 16 + g;
                    const int col = nf * 8 + c2;
                    atomicAdd(&sHg[r0 * HG_STRIDE + col],           acc[i][nf][0]);
                    atomicAdd(&sHg[r0 * HG_STRIDE + col + 1],       acc[i][nf][1]);
                    atomicAdd(&sHg[(r0 + 8) * HG_STRIDE + col],     acc[i][nf][2]);
                    atomicAdd(&sHg[(r0 + 8) * HG_STRIDE + col + 1], acc[i][nf][3]);
                }
        }
        __syncthreads();

        // ---- fused gating + h update (4 units/thread) ----
        float ex_r[4] = {exr.x, exr.y, exr.z, exr.w};
        float ex_z[4] = {exz.x, exz.y, exz.z, exz.w};
        float ex_n[4] = {exn.x, exn.y, exn.z, exn.w};
        float hp[4]   = {hpv.x, hpv.y, hpv.z, hpv.w};
        float outv[4];
#pragma unroll
        for (int uu = 0; uu < 4; uu++) {
            const int u = u0 + uu;
            const int j = j0 + u;
            const float hr = sHg[er * HG_STRIDE + u];
            const float hz = sHg[er * HG_STRIDE + 16 + u];
            const float hn = sHg[er * HG_STRIDE + 32 + u];
            const float rg = sigf(ex_r[uu] + hr + b_ih[j] + b_hh[j]);
            const float zg = sigf(ex_z[uu] + hz + b_ih[HID + j] + b_hh[HID + j]);
            const float ng = tanhf(ex_n[uu] + b_ih[2 * HID + j] + rg * (hn + b_hh[2 * HID + j]));
            outv[uu] = (1.0f - zg) * ng + zg * hp[uu];
        }
        // write new h: linear fp32 plane + fragment-major bf16 planes (write plane wp)
        __stcg(reinterpret_cast<float4 *>(&g_hlin[wp][hoff]),
               make_float4(outv[0], outv[1], outv[2], outv[3]));
        {
            unsigned *fH = g_hfh[wp] + fragW;
            unsigned *fL = g_hfl[wp] + fragW;
            __nv_bfloat16 h0, h1, l0_, l1_;
            split2(outv[0], h0, l0_); split2(outv[1], h1, l1_);
            __stcg(fH, pk(h0, h1));
            __stcg(fL, pk(l0_, l1_));
            split2(outv[2], h0, l0_); split2(outv[3], h1, l1_);
            __stcg(fH + 4, pk(h0, h1));   // next lane, same word
            __stcg(fL + 4, pk(l0_, l1_));
        }

        grid_bar(bt, (unsigned)(t + 1));
    }
}

// ---------------- kernel: zero h planes + reset barrier state ----------------
__global__ void k_zero() {
    int i = blockIdx.x * blockDim.x + threadIdx.x;
    if (i < 16 * 64 * 32 * 4) {
        g_hfh[0][i] = 0u;
        g_hfl[0][i] = 0u;
    }
    if (i < BATCH * HID) g_hlin[0][i] = 0.0f;
    if (i == 0) { g_count2[0] = 0; g_count2[1] = 0; g_phase2[0] = 0; g_phase2[1] = 0; }
}

// ---------------- kernel: out = h_final @ W_dense^T + b_dense ----------------
__global__ void k_dense(const float *__restrict__ Wd, const float *__restrict__ bd,
                        float *__restrict__ out) {
    const int gw   = (blockIdx.x * (blockDim.x >> 5)) + (threadIdx.x >> 5);
    const int lane = threadIdx.x & 31;
    if (gw >= BATCH * 2) return;
    const int b = gw >> 1, o = gw & 1;
    const float *h = g_hlin[0];   // t=511 (rp=1) wrote plane 0
    float s = 0.0f;
    for (int i = lane; i < HID; i += 32) s += h[b * HID + i] * Wd[o * HID + i];
#pragma unroll
    for (int off = 16; off > 0; off >>= 1) s += __shfl_xor_sync(0xFFFFFFFFu, s, off);
    if (lane == 0) out[b * 2 + o] = s + bd[o];
}

// ---------------- launch ----------------
extern "C" void kernel_launch(void *const *d_in, const int *in_sizes, int n_in,
                              void *d_out, int out_size) {
    const int   *inputs  = (const int *)d_in[0];
    const float *emb     = (const float *)d_in[1];
    const float *W_ih    = (const float *)d_in[2];
    const float *W_hh    = (const float *)d_in[3];
    const float *b_ih    = (const float *)d_in[4];
    const float *b_hh    = (const float *)d_in[5];
    const float *W_dense = (const float *)d_in[6];
    const float *b_dense = (const float *)d_in[7];
    float *out = (float *)d_out;

    cudaFuncSetAttribute(k_scan, cudaFuncAttributeMaxDynamicSharedMemorySize, SMEM_TOTAL);

    k_split<<<6144, 1024>>>(W_ih, W_hh);
    k_vocab<<<dim3(24, 250), 256>>>(emb);
    k_zero<<<256, 1024>>>();
    k_scan<<<NCTA, 512, SMEM_TOTAL>>>(inputs, b_ih, b_hh);
    k_dense<<<64, 256>>>(W_dense, b_dense, out);
}